// round 1
// baseline (speedup 1.0000x reference)
#include <cuda_runtime.h>
#include <math.h>

#define NB 4
#define NS 2048
#define ND 1024
#define NH 16
#define HDIM 64
#define NM (NB*NS)   // 8192 rows

// Scratch (allocation-free rule: __device__ globals). ~134 MB total.
__device__ __align__(256) float g_Q[(size_t)NB*NH*NS*HDIM];
__device__ __align__(256) float g_K[(size_t)NB*NH*NS*HDIM];
__device__ __align__(256) float g_V[(size_t)NB*NH*NS*HDIM];
__device__ __align__(256) float g_AO[(size_t)NB*NS*ND];

// ---------------------------------------------------------------------------
// C = A @ W^T + bias.  A:[M,K] row-major, W:[N,K] row-major.
// amode: 0 -> A = Ain param, 1 -> A = g_AO
// cmode: 0 -> Cout[m*N+n]
//        1/2/3 -> write per-head layout into g_Q/g_K/g_V:
//                 ((b*NH+h)*NS+s)*HDIM + hd  with b=m>>11, s=m&2047, h=n>>6, hd=n&63
// ---------------------------------------------------------------------------
__global__ __launch_bounds__(256) void gemm_bias(
    const float* __restrict__ Ain, const float* __restrict__ W,
    const float* __restrict__ bias, float* __restrict__ Cout,
    int amode, int cmode)
{
    constexpr int BM = 128, BN = 128, BK = 16, K = ND, N = ND;
    __shared__ float As[BK][BM];
    __shared__ float Bs[BK][BN];

    const float* A = amode ? g_AO : Ain;
    const int tid = threadIdx.x;
    const int m0 = blockIdx.y * BM;
    const int n0 = blockIdx.x * BN;
    const int ty = tid >> 4;      // 0..15
    const int tx = tid & 15;      // 0..15

    float acc[8][8];
#pragma unroll
    for (int i = 0; i < 8; i++)
#pragma unroll
        for (int j = 0; j < 8; j++) acc[i][j] = 0.0f;

    const float* Ap = A + (size_t)m0 * K;
    const float* Wp = W + (size_t)n0 * K;

    for (int k0 = 0; k0 < K; k0 += BK) {
#pragma unroll
        for (int i = 0; i < 2; i++) {
            int idx = tid + i * 256;       // 0..511
            int row = idx >> 2;            // 0..127
            int kq  = (idx & 3) << 2;      // 0,4,8,12
            float4 av = *(const float4*)(Ap + (size_t)row * K + k0 + kq);
            As[kq + 0][row] = av.x; As[kq + 1][row] = av.y;
            As[kq + 2][row] = av.z; As[kq + 3][row] = av.w;
            float4 bv = *(const float4*)(Wp + (size_t)row * K + k0 + kq);
            Bs[kq + 0][row] = bv.x; Bs[kq + 1][row] = bv.y;
            Bs[kq + 2][row] = bv.z; Bs[kq + 3][row] = bv.w;
        }
        __syncthreads();

#pragma unroll
        for (int kk = 0; kk < BK; kk++) {
            float a[8], b[8];
            *(float4*)&a[0] = *(const float4*)&As[kk][ty * 8];
            *(float4*)&a[4] = *(const float4*)&As[kk][ty * 8 + 4];
            *(float4*)&b[0] = *(const float4*)&Bs[kk][tx * 8];
            *(float4*)&b[4] = *(const float4*)&Bs[kk][tx * 8 + 4];
#pragma unroll
            for (int i = 0; i < 8; i++)
#pragma unroll
                for (int j = 0; j < 8; j++)
                    acc[i][j] += a[i] * b[j];
        }
        __syncthreads();
    }

    // bias preload
    float bv[8];
#pragma unroll
    for (int j = 0; j < 8; j++) bv[j] = bias[n0 + tx * 8 + j];

#pragma unroll
    for (int i = 0; i < 8; i++) {
        int m = m0 + ty * 8 + i;
#pragma unroll
        for (int j = 0; j < 8; j++) {
            int n = n0 + tx * 8 + j;
            float v = acc[i][j] + bv[j];
            if (cmode == 0) {
                Cout[(size_t)m * N + n] = v;
            } else {
                float* base = (cmode == 1) ? g_Q : (cmode == 2) ? g_K : g_V;
                int bb = m >> 11, ss = m & 2047;
                int h = n >> 6, hd = n & 63;
                base[(((size_t)(bb * NH + h)) * NS + ss) * HDIM + hd] = v;
            }
        }
    }
}

// ---------------------------------------------------------------------------
// Flash attention, fp32, causal. grid = (NS/64, NB*NH), 256 threads.
// Per block: 64 q-rows of one (b,h). Thread t -> row r=t>>2, quarter sub=t&3
// (owns 16 of 64 k-cols / head-dims). Online softmax across k-tiles of 64.
// ---------------------------------------------------------------------------
#define QS_STRIDE 65
#define KST_STRIDE 68   // d-major K tile, stride mult of 4 for float4 reads
#define PS_STRIDE 65
#define ATTN_SMEM ((64*QS_STRIDE + 64*KST_STRIDE + 64*PS_STRIDE + 64*64) * 4)

__global__ __launch_bounds__(256) void flash_attn()
{
    extern __shared__ float sm[];
    float* Qs  = sm;                      // [64][65]  (r, d)
    float* Kst = Qs  + 64 * QS_STRIDE;    // [64][68]  (d, kcol)
    float* Ps  = Kst + 64 * KST_STRIDE;   // [64][65]  (r, k)
    float* Vs  = Ps  + 64 * PS_STRIDE;    // [64][64]  (k, d)

    const int bh = blockIdx.y;            // 0..63
    const int qt = blockIdx.x;            // 0..31
    const int tid = threadIdx.x;
    const int r   = tid >> 2;             // 0..63
    const int sub = tid & 3;              // 0..3

    const float* Qb = g_Q + (size_t)bh * NS * HDIM;
    const float* Kb = g_K + (size_t)bh * NS * HDIM;
    const float* Vb = g_V + (size_t)bh * NS * HDIM;

    const int q0 = qt * 64;

    // Load Q tile, pre-scaled by 1/sqrt(HD) = 0.125
#pragma unroll
    for (int i = 0; i < 16; i++) {
        int idx = i * 256 + tid;
        int row = idx >> 6, d = idx & 63;
        Qs[row * QS_STRIDE + d] = Qb[(size_t)(q0 + row) * HDIM + d] * 0.125f;
    }

    float acc[16];
#pragma unroll
    for (int j = 0; j < 16; j++) acc[j] = 0.0f;
    float mrow = -INFINITY, lrow = 0.0f;

    for (int kt = 0; kt <= qt; kt++) {
        const int k0 = kt * 64;

        // Load K (d-major) and V (k-major) tiles
#pragma unroll
        for (int i = 0; i < 16; i++) {
            int idx = i * 256 + tid;
            int row = idx >> 6, d = idx & 63;
            Kst[d * KST_STRIDE + row] = Kb[(size_t)(k0 + row) * HDIM + d];
            Vs[row * 64 + d]          = Vb[(size_t)(k0 + row) * HDIM + d];
        }
        __syncthreads();

        // Scores: s[j] = sum_d Qs[r][d] * K[k0+sub*16+j][d]
        float s[16];
#pragma unroll
        for (int j = 0; j < 16; j++) s[j] = 0.0f;
        const float* qrow = &Qs[r * QS_STRIDE];
#pragma unroll 4
        for (int d = 0; d < 64; d++) {
            float qd = qrow[d];
            const float4* kp = (const float4*)&Kst[d * KST_STRIDE + sub * 16];
            float4 k0v = kp[0], k1v = kp[1], k2v = kp[2], k3v = kp[3];
            s[0]  += qd * k0v.x; s[1]  += qd * k0v.y; s[2]  += qd * k0v.z; s[3]  += qd * k0v.w;
            s[4]  += qd * k1v.x; s[5]  += qd * k1v.y; s[6]  += qd * k1v.z; s[7]  += qd * k1v.w;
            s[8]  += qd * k2v.x; s[9]  += qd * k2v.y; s[10] += qd * k2v.z; s[11] += qd * k2v.w;
            s[12] += qd * k3v.x; s[13] += qd * k3v.y; s[14] += qd * k3v.z; s[15] += qd * k3v.w;
        }

        // Causal mask (only the diagonal tile needs it)
        if (kt == qt) {
            int qg = q0 + r;
#pragma unroll
            for (int j = 0; j < 16; j++) {
                int kg = k0 + sub * 16 + j;
                if (kg > qg) s[j] = -INFINITY;
            }
        }

        // Online softmax: reduce across the 4 threads of this row (lanes xor 1,2)
        float tmax = -INFINITY;
#pragma unroll
        for (int j = 0; j < 16; j++) tmax = fmaxf(tmax, s[j]);
        tmax = fmaxf(tmax, __shfl_xor_sync(0xffffffffu, tmax, 1));
        tmax = fmaxf(tmax, __shfl_xor_sync(0xffffffffu, tmax, 2));
        float newm = fmaxf(mrow, tmax);

        float p[16], psum = 0.0f;
#pragma unroll
        for (int j = 0; j < 16; j++) {
            p[j] = __expf(s[j] - newm);
            psum += p[j];
        }
        psum += __shfl_xor_sync(0xffffffffu, psum, 1);
        psum += __shfl_xor_sync(0xffffffffu, psum, 2);

        float corr = __expf(mrow - newm);
        lrow = lrow * corr + psum;
        mrow = newm;
#pragma unroll
        for (int j = 0; j < 16; j++) acc[j] *= corr;

        // Stage P to shared for the AV product
#pragma unroll
        for (int j = 0; j < 16; j++)
            Ps[r * PS_STRIDE + sub * 16 + j] = p[j];
        __syncthreads();

        // acc[d] += sum_k P[r][k] * V[k][d], thread owns d = sub*16 .. +15
        const float* prow = &Ps[r * PS_STRIDE];
#pragma unroll 4
        for (int k = 0; k < 64; k++) {
            float pv = prow[k];
            const float4* vp = (const float4*)&Vs[k * 64 + sub * 16];
            float4 v0 = vp[0], v1 = vp[1], v2 = vp[2], v3 = vp[3];
            acc[0]  += pv * v0.x; acc[1]  += pv * v0.y; acc[2]  += pv * v0.z; acc[3]  += pv * v0.w;
            acc[4]  += pv * v1.x; acc[5]  += pv * v1.y; acc[6]  += pv * v1.z; acc[7]  += pv * v1.w;
            acc[8]  += pv * v2.x; acc[9]  += pv * v2.y; acc[10] += pv * v2.z; acc[11] += pv * v2.w;
            acc[12] += pv * v3.x; acc[13] += pv * v3.y; acc[14] += pv * v3.z; acc[15] += pv * v3.w;
        }
        __syncthreads();
    }

    // Normalize and write to g_AO in [B,S,D] layout (D = h*64 + hd)
    float invl = 1.0f / lrow;
    int b = bh >> 4, h = bh & 15;
    float* Ob = g_AO + ((size_t)(b * NS + q0 + r)) * ND + h * HDIM + sub * 16;
    float4 o;
#pragma unroll
    for (int q = 0; q < 4; q++) {
        o.x = acc[q * 4 + 0] * invl;
        o.y = acc[q * 4 + 1] * invl;
        o.z = acc[q * 4 + 2] * invl;
        o.w = acc[q * 4 + 3] * invl;
        *(float4*)&Ob[q * 4] = o;
    }
}

// ---------------------------------------------------------------------------
extern "C" void kernel_launch(void* const* d_in, const int* in_sizes, int n_in,
                              void* d_out, int out_size)
{
    const float* x    = (const float*)d_in[0];
    const float* wq_w = (const float*)d_in[1];
    const float* wq_b = (const float*)d_in[2];
    const float* wk_w = (const float*)d_in[3];
    const float* wk_b = (const float*)d_in[4];
    const float* wv_w = (const float*)d_in[5];
    const float* wv_b = (const float*)d_in[6];
    const float* wo_w = (const float*)d_in[7];
    const float* wo_b = (const float*)d_in[8];
    float* out = (float*)d_out;

    dim3 gemm_grid(ND / 128, NM / 128);   // (8, 64)

    // QKV projections -> per-head scratch
    gemm_bias<<<gemm_grid, 256>>>(x, wq_w, wq_b, nullptr, 0, 1);
    gemm_bias<<<gemm_grid, 256>>>(x, wk_w, wk_b, nullptr, 0, 2);
    gemm_bias<<<gemm_grid, 256>>>(x, wv_w, wv_b, nullptr, 0, 3);

    // Causal flash attention
    cudaFuncSetAttribute(flash_attn, cudaFuncAttributeMaxDynamicSharedMemorySize,
                         ATTN_SMEM);
    flash_attn<<<dim3(NS / 64, NB * NH), 256, ATTN_SMEM>>>();

    // Output projection -> d_out
    gemm_bias<<<gemm_grid, 256>>>(nullptr, wo_w, wo_b, out, 1, 0);
}

// round 2
// speedup vs baseline: 1.2772x; 1.2772x over previous
#include <cuda_runtime.h>
#include <math.h>
#include <stdint.h>

#define NB 4
#define NS 2048
#define ND 1024
#define NH 16
#define HDIM 64
#define NM (NB*NS)   // 8192 rows

// Scratch (allocation-free rule: __device__ globals). ~134 MB total.
__device__ __align__(256) float g_Q[(size_t)NB*NH*NS*HDIM];
__device__ __align__(256) float g_K[(size_t)NB*NH*NS*HDIM];
__device__ __align__(256) float g_V[(size_t)NB*NH*NS*HDIM];
__device__ __align__(256) float g_AO[(size_t)NB*NS*ND];

__device__ __forceinline__ float to_tf32(float x) {
    float r;
    asm("cvt.rna.tf32.f32 %0, %1;" : "=f"(r) : "f"(x));
    return r;
}

__device__ __forceinline__ void mma_tf32(float d[4], const uint32_t a[4],
                                         const uint32_t b[2]) {
    asm volatile(
        "mma.sync.aligned.m16n8k8.row.col.f32.tf32.tf32.f32 "
        "{%0,%1,%2,%3},{%4,%5,%6,%7},{%8,%9},{%0,%1,%2,%3};"
        : "+f"(d[0]), "+f"(d[1]), "+f"(d[2]), "+f"(d[3])
        : "r"(a[0]), "r"(a[1]), "r"(a[2]), "r"(a[3]),
          "r"(b[0]), "r"(b[1]));
}

// ---------------------------------------------------------------------------
// C = A @ W^T + bias, TF32 tensor cores.  A:[M,K] row-major, W:[N,K] row-major.
// CTA tile 128x128x32, 8 warps (2 m x 4 n), warp tile 64x32, mma m16n8k8.
// amode: 0 -> A = Ain, 1 -> A = g_AO
// cmode: 0 -> Cout[m*N+n];  1/2/3 -> scatter to g_Q/g_K/g_V per-head layout.
// ---------------------------------------------------------------------------
__global__ __launch_bounds__(256, 2) void gemm_tf32(
    const float* __restrict__ Ain, const float* __restrict__ W,
    const float* __restrict__ bias, float* __restrict__ Cout,
    int amode, int cmode)
{
    constexpr int BM = 128, BN = 128, BK = 32, K = ND, N = ND;
    constexpr int SS = 36;                 // row stride (pad 4): conflict-free frags
    __shared__ float As[BM * SS];          // [m][k]
    __shared__ float Bs[BN * SS];          // [n][k]

    const float* A = amode ? g_AO : Ain;
    const int tid  = threadIdx.x;
    const int lane = tid & 31;
    const int wid  = tid >> 5;
    const int wm   = wid & 1;              // 0..1
    const int wn   = wid >> 1;             // 0..3
    const int m0   = blockIdx.y * BM;
    const int n0   = blockIdx.x * BN;
    const int g    = lane >> 2;            // groupID 0..7
    const int tig  = lane & 3;             // 0..3

    float acc[4][4][4];
#pragma unroll
    for (int i = 0; i < 4; i++)
#pragma unroll
        for (int j = 0; j < 4; j++)
#pragma unroll
            for (int c = 0; c < 4; c++) acc[i][j][c] = 0.0f;

    const float* Ap = A + (size_t)m0 * K;
    const float* Wp = W + (size_t)n0 * K;

    // thread -> 4 float4 slots per tile: row = slot>>3, kq = (slot&7)*4
    int lrow[4], lkq[4];
#pragma unroll
    for (int i = 0; i < 4; i++) {
        int slot = tid + i * 256;
        lrow[i] = slot >> 3;
        lkq[i]  = (slot & 7) << 2;
    }

    float4 ra[4], rb[4];
#pragma unroll
    for (int i = 0; i < 4; i++) {
        ra[i] = *(const float4*)(Ap + (size_t)lrow[i] * K + lkq[i]);
        rb[i] = *(const float4*)(Wp + (size_t)lrow[i] * K + lkq[i]);
    }

    for (int k0 = 0; k0 < K; k0 += BK) {
        // store (already-loaded) tiles, converted to tf32
#pragma unroll
        for (int i = 0; i < 4; i++) {
            float4 a = ra[i], b = rb[i];
            a.x = to_tf32(a.x); a.y = to_tf32(a.y);
            a.z = to_tf32(a.z); a.w = to_tf32(a.w);
            b.x = to_tf32(b.x); b.y = to_tf32(b.y);
            b.z = to_tf32(b.z); b.w = to_tf32(b.w);
            *(float4*)&As[lrow[i] * SS + lkq[i]] = a;
            *(float4*)&Bs[lrow[i] * SS + lkq[i]] = b;
        }
        __syncthreads();

        // prefetch next tile
        if (k0 + BK < K) {
#pragma unroll
            for (int i = 0; i < 4; i++) {
                ra[i] = *(const float4*)(Ap + (size_t)lrow[i] * K + k0 + BK + lkq[i]);
                rb[i] = *(const float4*)(Wp + (size_t)lrow[i] * K + k0 + BK + lkq[i]);
            }
        }

#pragma unroll
        for (int k8 = 0; k8 < BK / 8; k8++) {
            const int kb = k8 * 8;
            uint32_t af[4][4];
#pragma unroll
            for (int mi = 0; mi < 4; mi++) {
                int m = wm * 64 + mi * 16;
                const float* p0 = &As[(m + g) * SS + kb + tig];
                const float* p1 = &As[(m + g + 8) * SS + kb + tig];
                af[mi][0] = __float_as_uint(p0[0]);
                af[mi][1] = __float_as_uint(p1[0]);
                af[mi][2] = __float_as_uint(p0[4]);
                af[mi][3] = __float_as_uint(p1[4]);
            }
            uint32_t bf[4][2];
#pragma unroll
            for (int ni = 0; ni < 4; ni++) {
                int n = wn * 32 + ni * 8;
                const float* p = &Bs[(n + g) * SS + kb + tig];
                bf[ni][0] = __float_as_uint(p[0]);
                bf[ni][1] = __float_as_uint(p[4]);
            }
#pragma unroll
            for (int mi = 0; mi < 4; mi++)
#pragma unroll
                for (int ni = 0; ni < 4; ni++)
                    mma_tf32(acc[mi][ni], af[mi], bf[ni]);
        }
        __syncthreads();
    }

    // Epilogue: c0,c1 at (row=g, col=2*tig+{0,1}); c2,c3 at row=g+8.
#pragma unroll
    for (int mi = 0; mi < 4; mi++) {
#pragma unroll
        for (int ni = 0; ni < 4; ni++) {
#pragma unroll
            for (int c = 0; c < 4; c++) {
                int m = m0 + wm * 64 + mi * 16 + g + (c >> 1) * 8;
                int n = n0 + wn * 32 + ni * 8 + tig * 2 + (c & 1);
                float v = acc[mi][ni][c] + bias[n];
                if (cmode == 0) {
                    Cout[(size_t)m * N + n] = v;
                } else {
                    float* base = (cmode == 1) ? g_Q : (cmode == 2) ? g_K : g_V;
                    int bb = m >> 11, ss = m & 2047;
                    int h = n >> 6, hd = n & 63;
                    base[(((size_t)(bb * NH + h)) * NS + ss) * HDIM + hd] = v;
                }
            }
        }
    }
}

// ---------------------------------------------------------------------------
// Flash attention, fp32, causal. grid = (NS/64, NB*NH), 256 threads.
// ---------------------------------------------------------------------------
#define QS_STRIDE 65
#define KST_STRIDE 68
#define PS_STRIDE 65
#define ATTN_SMEM ((64*QS_STRIDE + 64*KST_STRIDE + 64*PS_STRIDE + 64*64) * 4)

__global__ __launch_bounds__(256) void flash_attn()
{
    extern __shared__ float sm[];
    float* Qs  = sm;                      // [64][65]  (r, d)
    float* Kst = Qs  + 64 * QS_STRIDE;    // [64][68]  (d, kcol)
    float* Ps  = Kst + 64 * KST_STRIDE;   // [64][65]  (r, k)
    float* Vs  = Ps  + 64 * PS_STRIDE;    // [64][64]  (k, d)

    const int bh = blockIdx.y;
    const int qt = blockIdx.x;
    const int tid = threadIdx.x;
    const int r   = tid >> 2;
    const int sub = tid & 3;

    const float* Qb = g_Q + (size_t)bh * NS * HDIM;
    const float* Kb = g_K + (size_t)bh * NS * HDIM;
    const float* Vb = g_V + (size_t)bh * NS * HDIM;

    const int q0 = qt * 64;

#pragma unroll
    for (int i = 0; i < 16; i++) {
        int idx = i * 256 + tid;
        int row = idx >> 6, d = idx & 63;
        Qs[row * QS_STRIDE + d] = Qb[(size_t)(q0 + row) * HDIM + d] * 0.125f;
    }

    float acc[16];
#pragma unroll
    for (int j = 0; j < 16; j++) acc[j] = 0.0f;
    float mrow = -INFINITY, lrow = 0.0f;

    for (int kt = 0; kt <= qt; kt++) {
        const int k0 = kt * 64;

#pragma unroll
        for (int i = 0; i < 16; i++) {
            int idx = i * 256 + tid;
            int row = idx >> 6, d = idx & 63;
            Kst[d * KST_STRIDE + row] = Kb[(size_t)(k0 + row) * HDIM + d];
            Vs[row * 64 + d]          = Vb[(size_t)(k0 + row) * HDIM + d];
        }
        __syncthreads();

        float s[16];
#pragma unroll
        for (int j = 0; j < 16; j++) s[j] = 0.0f;
        const float* qrow = &Qs[r * QS_STRIDE];
#pragma unroll 4
        for (int d = 0; d < 64; d++) {
            float qd = qrow[d];
            const float4* kp = (const float4*)&Kst[d * KST_STRIDE + sub * 16];
            float4 k0v = kp[0], k1v = kp[1], k2v = kp[2], k3v = kp[3];
            s[0]  += qd * k0v.x; s[1]  += qd * k0v.y; s[2]  += qd * k0v.z; s[3]  += qd * k0v.w;
            s[4]  += qd * k1v.x; s[5]  += qd * k1v.y; s[6]  += qd * k1v.z; s[7]  += qd * k1v.w;
            s[8]  += qd * k2v.x; s[9]  += qd * k2v.y; s[10] += qd * k2v.z; s[11] += qd * k2v.w;
            s[12] += qd * k3v.x; s[13] += qd * k3v.y; s[14] += qd * k3v.z; s[15] += qd * k3v.w;
        }

        if (kt == qt) {
            int qg = q0 + r;
#pragma unroll
            for (int j = 0; j < 16; j++) {
                int kg = k0 + sub * 16 + j;
                if (kg > qg) s[j] = -INFINITY;
            }
        }

        float tmax = -INFINITY;
#pragma unroll
        for (int j = 0; j < 16; j++) tmax = fmaxf(tmax, s[j]);
        tmax = fmaxf(tmax, __shfl_xor_sync(0xffffffffu, tmax, 1));
        tmax = fmaxf(tmax, __shfl_xor_sync(0xffffffffu, tmax, 2));
        float newm = fmaxf(mrow, tmax);

        float p[16], psum = 0.0f;
#pragma unroll
        for (int j = 0; j < 16; j++) {
            p[j] = __expf(s[j] - newm);
            psum += p[j];
        }
        psum += __shfl_xor_sync(0xffffffffu, psum, 1);
        psum += __shfl_xor_sync(0xffffffffu, psum, 2);

        float corr = __expf(mrow - newm);
        lrow = lrow * corr + psum;
        mrow = newm;
#pragma unroll
        for (int j = 0; j < 16; j++) acc[j] *= corr;

#pragma unroll
        for (int j = 0; j < 16; j++)
            Ps[r * PS_STRIDE + sub * 16 + j] = p[j];
        __syncthreads();

        const float* prow = &Ps[r * PS_STRIDE];
#pragma unroll 4
        for (int k = 0; k < 64; k++) {
            float pv = prow[k];
            const float4* vp = (const float4*)&Vs[k * 64 + sub * 16];
            float4 v0 = vp[0], v1 = vp[1], v2 = vp[2], v3 = vp[3];
            acc[0]  += pv * v0.x; acc[1]  += pv * v0.y; acc[2]  += pv * v0.z; acc[3]  += pv * v0.w;
            acc[4]  += pv * v1.x; acc[5]  += pv * v1.y; acc[6]  += pv * v1.z; acc[7]  += pv * v1.w;
            acc[8]  += pv * v2.x; acc[9]  += pv * v2.y; acc[10] += pv * v2.z; acc[11] += pv * v2.w;
            acc[12] += pv * v3.x; acc[13] += pv * v3.y; acc[14] += pv * v3.z; acc[15] += pv * v3.w;
        }
        __syncthreads();
    }

    float invl = 1.0f / lrow;
    int b = bh >> 4, h = bh & 15;
    float* Ob = g_AO + ((size_t)(b * NS + q0 + r)) * ND + h * HDIM + sub * 16;
    float4 o;
#pragma unroll
    for (int q = 0; q < 4; q++) {
        o.x = acc[q * 4 + 0] * invl;
        o.y = acc[q * 4 + 1] * invl;
        o.z = acc[q * 4 + 2] * invl;
        o.w = acc[q * 4 + 3] * invl;
        *(float4*)&Ob[q * 4] = o;
    }
}

// ---------------------------------------------------------------------------
extern "C" void kernel_launch(void* const* d_in, const int* in_sizes, int n_in,
                              void* d_out, int out_size)
{
    const float* x    = (const float*)d_in[0];
    const float* wq_w = (const float*)d_in[1];
    const float* wq_b = (const float*)d_in[2];
    const float* wk_w = (const float*)d_in[3];
    const float* wk_b = (const float*)d_in[4];
    const float* wv_w = (const float*)d_in[5];
    const float* wv_b = (const float*)d_in[6];
    const float* wo_w = (const float*)d_in[7];
    const float* wo_b = (const float*)d_in[8];
    float* out = (float*)d_out;

    dim3 gemm_grid(ND / 128, NM / 128);   // (8, 64)

    gemm_tf32<<<gemm_grid, 256>>>(x, wq_w, wq_b, nullptr, 0, 1);
    gemm_tf32<<<gemm_grid, 256>>>(x, wk_w, wk_b, nullptr, 0, 2);
    gemm_tf32<<<gemm_grid, 256>>>(x, wv_w, wv_b, nullptr, 0, 3);

    cudaFuncSetAttribute(flash_attn, cudaFuncAttributeMaxDynamicSharedMemorySize,
                         ATTN_SMEM);
    flash_attn<<<dim3(NS / 64, NB * NH), 256, ATTN_SMEM>>>();

    gemm_tf32<<<gemm_grid, 256>>>(nullptr, wo_w, wo_b, out, 1, 0);
}

// round 3
// speedup vs baseline: 4.9902x; 3.9070x over previous
#include <cuda_runtime.h>
#include <math.h>
#include <stdint.h>

#define NB 4
#define NS 2048
#define ND 1024
#define NH 16
#define HDIM 64
#define NM (NB*NS)   // 8192 rows

// Scratch (allocation-free rule: __device__ globals). ~134 MB total.
// g_Q: [bh][s][d]            (natural)
// g_K: [bh][d][key]          with key permuted within each 64-block:
//                            pos = (key & ~63) + (key&7)*8 + ((key>>3)&7)
// g_V: [bh][key][d']         d' = (d&7)*8 + (d>>3)
__device__ __align__(256) float g_Q[(size_t)NB*NH*NS*HDIM];
__device__ __align__(256) float g_K[(size_t)NB*NH*NS*HDIM];
__device__ __align__(256) float g_V[(size_t)NB*NH*NS*HDIM];
__device__ __align__(256) float g_AO[(size_t)NB*NS*ND];

__device__ __forceinline__ float to_tf32(float x) {
    float r;
    asm("cvt.rna.tf32.f32 %0, %1;" : "=f"(r) : "f"(x));
    return r;
}

__device__ __forceinline__ void mma_tf32(float d[4], const uint32_t a[4],
                                         const uint32_t b[2]) {
    asm volatile(
        "mma.sync.aligned.m16n8k8.row.col.f32.tf32.tf32.f32 "
        "{%0,%1,%2,%3},{%4,%5,%6,%7},{%8,%9},{%0,%1,%2,%3};"
        : "+f"(d[0]), "+f"(d[1]), "+f"(d[2]), "+f"(d[3])
        : "r"(a[0]), "r"(a[1]), "r"(a[2]), "r"(a[3]),
          "r"(b[0]), "r"(b[1]));
}

__device__ __forceinline__ void cp16(float* dst, const float* src) {
    uint32_t d = (uint32_t)__cvta_generic_to_shared(dst);
    asm volatile("cp.async.cg.shared.global [%0], [%1], 16;" :: "r"(d), "l"(src));
}
__device__ __forceinline__ void cp_commit() {
    asm volatile("cp.async.commit_group;" ::: "memory");
}
__device__ __forceinline__ void cp_wait0() {
    asm volatile("cp.async.wait_group 0;" ::: "memory");
}

// ---------------------------------------------------------------------------
// C = A @ W^T + bias, TF32 tensor cores.  A:[M,K] rm, W:[N,K] rm.
// CTA 128x128x32, 8 warps (2m x 4n), warp 64x32, mma m16n8k8.
// Smem tiles stored k-interleaved: col k' = (k&3)*8 + (k>>2), row stride 34
// -> each frag pair is one conflict-free LDS.64.
// ---------------------------------------------------------------------------
__global__ __launch_bounds__(256, 2) void gemm_tf32(
    const float* __restrict__ Ain, const float* __restrict__ W,
    const float* __restrict__ bias, float* __restrict__ Cout,
    int amode, int cmode)
{
    constexpr int BM = 128, BN = 128, BK = 32, K = ND, N = ND;
    constexpr int SS = 34;
    __shared__ float As[BM * SS];
    __shared__ float Bs[BN * SS];

    const float* A = amode ? g_AO : Ain;
    const int tid  = threadIdx.x;
    const int lane = tid & 31;
    const int wid  = tid >> 5;
    const int wm   = wid & 1;
    const int wn   = wid >> 1;
    const int m0   = blockIdx.y * BM;
    const int n0   = blockIdx.x * BN;
    const int g    = lane >> 2;
    const int tig  = lane & 3;

    float acc[4][4][4];
#pragma unroll
    for (int i = 0; i < 4; i++)
#pragma unroll
        for (int j = 0; j < 4; j++)
#pragma unroll
            for (int c = 0; c < 4; c++) acc[i][j][c] = 0.0f;

    const float* Ap = A + (size_t)m0 * K;
    const float* Wp = W + (size_t)n0 * K;

    int lrow[4], lq[4];
#pragma unroll
    for (int i = 0; i < 4; i++) {
        int slot = tid + i * 256;
        lrow[i] = slot >> 3;
        lq[i]   = slot & 7;      // k = 4*lq .. 4*lq+3
    }

    float4 ra[4], rb[4];
#pragma unroll
    for (int i = 0; i < 4; i++) {
        ra[i] = *(const float4*)(Ap + (size_t)lrow[i] * K + lq[i] * 4);
        rb[i] = *(const float4*)(Wp + (size_t)lrow[i] * K + lq[i] * 4);
    }

    for (int k0 = 0; k0 < K; k0 += BK) {
#pragma unroll
        for (int i = 0; i < 4; i++) {
            // k = 4*lq+e  ->  k' = e*8 + lq
            float av[4] = { ra[i].x, ra[i].y, ra[i].z, ra[i].w };
            float bv[4] = { rb[i].x, rb[i].y, rb[i].z, rb[i].w };
#pragma unroll
            for (int e = 0; e < 4; e++) {
                As[lrow[i] * SS + e * 8 + lq[i]] = to_tf32(av[e]);
                Bs[lrow[i] * SS + e * 8 + lq[i]] = to_tf32(bv[e]);
            }
        }
        __syncthreads();

        if (k0 + BK < K) {
#pragma unroll
            for (int i = 0; i < 4; i++) {
                ra[i] = *(const float4*)(Ap + (size_t)lrow[i] * K + k0 + BK + lq[i] * 4);
                rb[i] = *(const float4*)(Wp + (size_t)lrow[i] * K + k0 + BK + lq[i] * 4);
            }
        }

#pragma unroll
        for (int s = 0; s < BK / 8; s++) {
            uint32_t af[4][4];
#pragma unroll
            for (int mi = 0; mi < 4; mi++) {
                int row = wm * 64 + mi * 16 + g;
                float2 lo0 = *(const float2*)&As[row * SS + tig * 8 + 2 * s];
                float2 lo1 = *(const float2*)&As[(row + 8) * SS + tig * 8 + 2 * s];
                af[mi][0] = __float_as_uint(lo0.x);
                af[mi][1] = __float_as_uint(lo1.x);
                af[mi][2] = __float_as_uint(lo0.y);
                af[mi][3] = __float_as_uint(lo1.y);
            }
            uint32_t bf[4][2];
#pragma unroll
            for (int ni = 0; ni < 4; ni++) {
                int row = wn * 32 + ni * 8 + g;
                float2 b = *(const float2*)&Bs[row * SS + tig * 8 + 2 * s];
                bf[ni][0] = __float_as_uint(b.x);
                bf[ni][1] = __float_as_uint(b.y);
            }
#pragma unroll
            for (int mi = 0; mi < 4; mi++)
#pragma unroll
                for (int ni = 0; ni < 4; ni++)
                    mma_tf32(acc[mi][ni], af[mi], bf[ni]);
        }
        __syncthreads();
    }

#pragma unroll
    for (int mi = 0; mi < 4; mi++) {
#pragma unroll
        for (int ni = 0; ni < 4; ni++) {
#pragma unroll
            for (int c = 0; c < 4; c++) {
                int m = m0 + wm * 64 + mi * 16 + g + (c >> 1) * 8;
                int n = n0 + wn * 32 + ni * 8 + tig * 2 + (c & 1);
                float v = acc[mi][ni][c] + bias[n];
                if (cmode == 0) {
                    Cout[(size_t)m * N + n] = v;
                } else {
                    int bb = m >> 11, ss = m & 2047;
                    int h = n >> 6, hd = n & 63;
                    if (cmode == 1) {
                        g_Q[(((size_t)(bb * NH + h)) * NS + ss) * HDIM + hd] = v;
                    } else if (cmode == 2) {
                        size_t off = (((size_t)(bb * NH + h)) * HDIM + hd) * NS
                                   + (ss & ~63) + ((ss & 7) * 8 + ((ss >> 3) & 7));
                        g_K[off] = to_tf32(v);
                    } else {
                        size_t off = (((size_t)(bb * NH + h)) * NS + ss) * HDIM
                                   + ((hd & 7) * 8 + (hd >> 3));
                        g_V[off] = to_tf32(v);
                    }
                }
            }
        }
    }
}

// ---------------------------------------------------------------------------
// Tensor-core flash attention, tf32 mma, causal.
// CTA: 128 q-rows of one (b,h); 8 warps x 16 rows. K-tiles of 64.
// grid = (16, 64).  Double-buffered cp.async K/V tiles.
// ---------------------------------------------------------------------------
#define KSS 68
#define FLASH_SMEM ((4*64*KSS + 8*16*KSS) * 4)   // 104448 B

__global__ __launch_bounds__(256, 1) void flash_attn_mma()
{
    extern __shared__ float sm[];
    float* KsA[2] = { sm,            sm + 64*KSS };
    float* VsA[2] = { sm + 2*64*KSS, sm + 3*64*KSS };
    float* Ps     = sm + 4*64*KSS;

    const int tid  = threadIdx.x;
    const int lane = tid & 31;
    const int wq   = tid >> 5;            // 0..7
    const int g    = lane >> 2;           // 0..7
    const int tig  = lane & 3;            // 0..3
    const int bh   = blockIdx.y;
    const int qt   = (int)gridDim.x - 1 - (int)blockIdx.x;  // heavy tiles first
    const int q0   = qt * 128;

    const float* Qb = g_Q + (size_t)bh * NS * HDIM;
    const float* Kb = g_K + (size_t)bh * HDIM * NS;   // [d][key(perm)]
    const float* Vb = g_V + (size_t)bh * NS * HDIM;   // [key][d(perm)]

    // ---- stage Q tile (128x64) into sm[0..128*KSS), build Q frags ----
#pragma unroll
    for (int i = 0; i < 8; i++) {
        int f4 = tid + i * 256;           // 0..2047
        int row = f4 >> 4, c = (f4 & 15) * 4;
        *(float4*)&sm[row * KSS + c] =
            *(const float4*)(Qb + (size_t)(q0 + row) * HDIM + c);
    }
    __syncthreads();

    float qf[8][4];
    {
        const float* Q0 = &sm[(wq * 16 + g) * KSS];
        const float* Q1 = &sm[(wq * 16 + g + 8) * KSS];
#pragma unroll
        for (int s = 0; s < 8; s++) {
            qf[s][0] = to_tf32(Q0[8 * s + tig] * 0.125f);
            qf[s][1] = to_tf32(Q1[8 * s + tig] * 0.125f);
            qf[s][2] = to_tf32(Q0[8 * s + tig + 4] * 0.125f);
            qf[s][3] = to_tf32(Q1[8 * s + tig + 4] * 0.125f);
        }
    }
    __syncthreads();

    const int ktmax = 2 * qt + 1;
    const int rmin  = q0 + wq * 16;

    auto prefetch = [&](int t) {
        int buf = t & 1;
        float* kd = KsA[buf];
        float* vd = VsA[buf];
        int kk0 = t * 64;
#pragma unroll
        for (int i = 0; i < 4; i++) {
            int f4 = tid + i * 256;       // 0..1023
            int row = f4 >> 4, c = (f4 & 15) * 4;
            cp16(&kd[row * KSS + c], Kb + (size_t)row * NS + kk0 + c);
            cp16(&vd[row * KSS + c], Vb + (size_t)(kk0 + row) * HDIM + c);
        }
    };

    prefetch(0);
    cp_commit();

    float oacc[8][4];
#pragma unroll
    for (int i = 0; i < 8; i++)
#pragma unroll
        for (int c = 0; c < 4; c++) oacc[i][c] = 0.0f;
    float m0 = -INFINITY, m1 = -INFINITY, l0 = 0.0f, l1 = 0.0f;
    float* Pw = Ps + wq * 16 * KSS;

    for (int kt = 0; kt <= ktmax; kt++) {
        cp_wait0();
        __syncthreads();
        if (kt < ktmax) { prefetch(kt + 1); cp_commit(); }

        const int k0 = kt * 64;
        if (k0 <= rmin + 15) {
            const float* K = KsA[kt & 1];
            const float* V = VsA[kt & 1];

            // ---- S = Q K^T ----
            float sacc[8][4];
#pragma unroll
            for (int i = 0; i < 8; i++)
#pragma unroll
                for (int c = 0; c < 4; c++) sacc[i][c] = 0.0f;

#pragma unroll
            for (int s = 0; s < 8; s++) {
                float k0a[8], k1a[8];
                const float* kr0 = &K[(8 * s + tig) * KSS + 8 * g];
                const float* kr1 = &K[(8 * s + tig + 4) * KSS + 8 * g];
                *(float4*)&k0a[0] = *(const float4*)&kr0[0];
                *(float4*)&k0a[4] = *(const float4*)&kr0[4];
                *(float4*)&k1a[0] = *(const float4*)&kr1[0];
                *(float4*)&k1a[4] = *(const float4*)&kr1[4];
                uint32_t a[4] = { __float_as_uint(qf[s][0]), __float_as_uint(qf[s][1]),
                                  __float_as_uint(qf[s][2]), __float_as_uint(qf[s][3]) };
#pragma unroll
                for (int nt = 0; nt < 8; nt++) {
                    uint32_t b[2] = { __float_as_uint(k0a[nt]), __float_as_uint(k1a[nt]) };
                    mma_tf32(sacc[nt], a, b);
                }
            }

            // ---- causal mask ----
            if (k0 + 63 > rmin) {
                int r0 = rmin + g, r1 = r0 + 8;
#pragma unroll
                for (int nt = 0; nt < 8; nt++) {
                    int c0 = k0 + 8 * nt + 2 * tig;
                    if (c0     > r0) sacc[nt][0] = -INFINITY;
                    if (c0 + 1 > r0) sacc[nt][1] = -INFINITY;
                    if (c0     > r1) sacc[nt][2] = -INFINITY;
                    if (c0 + 1 > r1) sacc[nt][3] = -INFINITY;
                }
            }

            // ---- online softmax ----
            float t0 = -INFINITY, t1 = -INFINITY;
#pragma unroll
            for (int nt = 0; nt < 8; nt++) {
                t0 = fmaxf(t0, fmaxf(sacc[nt][0], sacc[nt][1]));
                t1 = fmaxf(t1, fmaxf(sacc[nt][2], sacc[nt][3]));
            }
            t0 = fmaxf(t0, __shfl_xor_sync(0xffffffffu, t0, 1));
            t0 = fmaxf(t0, __shfl_xor_sync(0xffffffffu, t0, 2));
            t1 = fmaxf(t1, __shfl_xor_sync(0xffffffffu, t1, 1));
            t1 = fmaxf(t1, __shfl_xor_sync(0xffffffffu, t1, 2));
            float nm0 = fmaxf(m0, t0), nm1 = fmaxf(m1, t1);
            float corr0 = __expf(m0 - nm0), corr1 = __expf(m1 - nm1);

            float ps0 = 0.0f, ps1 = 0.0f;
#pragma unroll
            for (int nt = 0; nt < 8; nt++) {
                float p0 = __expf(sacc[nt][0] - nm0);
                float p1 = __expf(sacc[nt][1] - nm0);
                float p2 = __expf(sacc[nt][2] - nm1);
                float p3 = __expf(sacc[nt][3] - nm1);
                ps0 += p0 + p1; ps1 += p2 + p3;
                float2 lo = { to_tf32(p0), to_tf32(p1) };
                float2 hi = { to_tf32(p2), to_tf32(p3) };
                *(float2*)&Pw[g * KSS + 8 * nt + 2 * tig] = lo;
                *(float2*)&Pw[(g + 8) * KSS + 8 * nt + 2 * tig] = hi;
            }
            ps0 += __shfl_xor_sync(0xffffffffu, ps0, 1);
            ps0 += __shfl_xor_sync(0xffffffffu, ps0, 2);
            ps1 += __shfl_xor_sync(0xffffffffu, ps1, 1);
            ps1 += __shfl_xor_sync(0xffffffffu, ps1, 2);
            l0 = l0 * corr0 + ps0;
            l1 = l1 * corr1 + ps1;
            m0 = nm0; m1 = nm1;
#pragma unroll
            for (int nt = 0; nt < 8; nt++) {
                oacc[nt][0] *= corr0; oacc[nt][1] *= corr0;
                oacc[nt][2] *= corr1; oacc[nt][3] *= corr1;
            }
            __syncwarp();

            // ---- O += P V ----
#pragma unroll
            for (int s = 0; s < 8; s++) {
                float v0a[8], v1a[8];
                const float* vr0 = &V[(8 * s + tig) * KSS + 8 * g];
                const float* vr1 = &V[(8 * s + tig + 4) * KSS + 8 * g];
                *(float4*)&v0a[0] = *(const float4*)&vr0[0];
                *(float4*)&v0a[4] = *(const float4*)&vr0[4];
                *(float4*)&v1a[0] = *(const float4*)&vr1[0];
                *(float4*)&v1a[4] = *(const float4*)&vr1[4];
                uint32_t a[4] = {
                    __float_as_uint(Pw[g * KSS + 8 * s + tig]),
                    __float_as_uint(Pw[(g + 8) * KSS + 8 * s + tig]),
                    __float_as_uint(Pw[g * KSS + 8 * s + tig + 4]),
                    __float_as_uint(Pw[(g + 8) * KSS + 8 * s + tig + 4]) };
#pragma unroll
                for (int nt = 0; nt < 8; nt++) {
                    uint32_t b[2] = { __float_as_uint(v0a[nt]), __float_as_uint(v1a[nt]) };
                    mma_tf32(oacc[nt], a, b);
                }
            }
            __syncwarp();
        }
    }

    // ---- epilogue ----
    float inv0 = 1.0f / l0, inv1 = 1.0f / l1;
    int b = bh >> 4, h = bh & 15;
    int row0 = q0 + wq * 16 + g;
    float* O0 = g_AO + ((size_t)(b * NS + row0)) * ND + h * HDIM;
    float* O1 = g_AO + ((size_t)(b * NS + row0 + 8)) * ND + h * HDIM;
#pragma unroll
    for (int nt = 0; nt < 8; nt++) {
        float2 lo = { oacc[nt][0] * inv0, oacc[nt][1] * inv0 };
        float2 hi = { oacc[nt][2] * inv1, oacc[nt][3] * inv1 };
        *(float2*)&O0[8 * nt + 2 * tig] = lo;
        *(float2*)&O1[8 * nt + 2 * tig] = hi;
    }
}

// ---------------------------------------------------------------------------
extern "C" void kernel_launch(void* const* d_in, const int* in_sizes, int n_in,
                              void* d_out, int out_size)
{
    const float* x    = (const float*)d_in[0];
    const float* wq_w = (const float*)d_in[1];
    const float* wq_b = (const float*)d_in[2];
    const float* wk_w = (const float*)d_in[3];
    const float* wk_b = (const float*)d_in[4];
    const float* wv_w = (const float*)d_in[5];
    const float* wv_b = (const float*)d_in[6];
    const float* wo_w = (const float*)d_in[7];
    const float* wo_b = (const float*)d_in[8];
    float* out = (float*)d_out;

    dim3 gemm_grid(ND / 128, NM / 128);   // (8, 64)

    gemm_tf32<<<gemm_grid, 256>>>(x, wq_w, wq_b, nullptr, 0, 1);
    gemm_tf32<<<gemm_grid, 256>>>(x, wk_w, wk_b, nullptr, 0, 2);
    gemm_tf32<<<gemm_grid, 256>>>(x, wv_w, wv_b, nullptr, 0, 3);

    cudaFuncSetAttribute(flash_attn_mma,
                         cudaFuncAttributeMaxDynamicSharedMemorySize, FLASH_SMEM);
    flash_attn_mma<<<dim3(NS / 128, NB * NH), 256, FLASH_SMEM>>>();

    gemm_tf32<<<gemm_grid, 256>>>(nullptr, wo_w, wo_b, out, 1, 0);
}

// round 4
// speedup vs baseline: 5.9397x; 1.1903x over previous
#include <cuda_runtime.h>
#include <math.h>
#include <stdint.h>

#define NB 4
#define NS 2048
#define ND 1024
#define NH 16
#define HDIM 64
#define NM (NB*NS)   // 8192 rows

// Scratch (allocation-free rule: __device__ globals). ~134 MB total.
// g_Q: [bh][s][d]            (natural)
// g_K: [bh][d][key]          key permuted per 64-block: pos=(k&7)*8+((k>>3)&7)
// g_V: [bh][key][d']         d' = (d&7)*8 + (d>>3)
__device__ __align__(256) float g_Q[(size_t)NB*NH*NS*HDIM];
__device__ __align__(256) float g_K[(size_t)NB*NH*NS*HDIM];
__device__ __align__(256) float g_V[(size_t)NB*NH*NS*HDIM];
__device__ __align__(256) float g_AO[(size_t)NB*NS*ND];

__device__ __forceinline__ float to_tf32(float x) {
    float r;
    asm("cvt.rna.tf32.f32 %0, %1;" : "=f"(r) : "f"(x));
    return r;
}

__device__ __forceinline__ void mma_tf32(float d[4], const uint32_t a[4],
                                         const uint32_t b[2]) {
    asm volatile(
        "mma.sync.aligned.m16n8k8.row.col.f32.tf32.tf32.f32 "
        "{%0,%1,%2,%3},{%4,%5,%6,%7},{%8,%9},{%0,%1,%2,%3};"
        : "+f"(d[0]), "+f"(d[1]), "+f"(d[2]), "+f"(d[3])
        : "r"(a[0]), "r"(a[1]), "r"(a[2]), "r"(a[3]),
          "r"(b[0]), "r"(b[1]));
}

__device__ __forceinline__ void cp16(float* dst, const float* src) {
    uint32_t d = (uint32_t)__cvta_generic_to_shared(dst);
    asm volatile("cp.async.cg.shared.global [%0], [%1], 16;" :: "r"(d), "l"(src));
}
__device__ __forceinline__ void cp_commit() {
    asm volatile("cp.async.commit_group;" ::: "memory");
}
__device__ __forceinline__ void cp_wait0() {
    asm volatile("cp.async.wait_group 0;" ::: "memory");
}

// ---------------------------------------------------------------------------
// C = A @ W^T + bias, TF32 tensor cores.  A:[M,K] rm, W:[N,K] rm.
// CTA 128x128x32, 8 warps (2m x 4n), warp 64x32, mma m16n8k8.
// fused=1: QKV fused launch, grid.x = 24; sel = bx>>3 picks {Wq,Wk,Wv} and
//          scatter mode; A tile identical across sel.
// fused=0: single GEMM (W0,b0), cmode0 applies.
// ---------------------------------------------------------------------------
__global__ __launch_bounds__(256, 2) void gemm_tf32(
    const float* __restrict__ Ain,
    const float* __restrict__ W0, const float* __restrict__ b0,
    const float* __restrict__ W1, const float* __restrict__ b1,
    const float* __restrict__ W2, const float* __restrict__ b2,
    float* __restrict__ Cout, int amode, int fused, int cmode0)
{
    constexpr int BM = 128, BN = 128, BK = 32, K = ND, N = ND;
    constexpr int SS = 34;
    __shared__ float As[BM * SS];
    __shared__ float Bs[BN * SS];

    const float* A = amode ? g_AO : Ain;
    int sel, nblk, cmode;
    const float* W;
    const float* bias;
    if (fused) {
        sel  = blockIdx.x >> 3;
        nblk = blockIdx.x & 7;
        W    = (sel == 0) ? W0 : (sel == 1) ? W1 : W2;
        bias = (sel == 0) ? b0 : (sel == 1) ? b1 : b2;
        cmode = sel + 1;
    } else {
        nblk = blockIdx.x;
        W = W0; bias = b0; cmode = cmode0;
    }

    const int tid  = threadIdx.x;
    const int lane = tid & 31;
    const int wid  = tid >> 5;
    const int wm   = wid & 1;
    const int wn   = wid >> 1;
    const int m0   = blockIdx.y * BM;
    const int n0   = nblk * BN;
    const int g    = lane >> 2;
    const int tig  = lane & 3;

    float acc[4][4][4];
#pragma unroll
    for (int i = 0; i < 4; i++)
#pragma unroll
        for (int j = 0; j < 4; j++)
#pragma unroll
            for (int c = 0; c < 4; c++) acc[i][j][c] = 0.0f;

    const float* Ap = A + (size_t)m0 * K;
    const float* Wp = W + (size_t)n0 * K;

    int lrow[4], lq[4];
#pragma unroll
    for (int i = 0; i < 4; i++) {
        int slot = tid + i * 256;
        lrow[i] = slot >> 3;
        lq[i]   = slot & 7;
    }

    float4 ra[4], rb[4];
#pragma unroll
    for (int i = 0; i < 4; i++) {
        ra[i] = *(const float4*)(Ap + (size_t)lrow[i] * K + lq[i] * 4);
        rb[i] = *(const float4*)(Wp + (size_t)lrow[i] * K + lq[i] * 4);
    }

    for (int k0 = 0; k0 < K; k0 += BK) {
#pragma unroll
        for (int i = 0; i < 4; i++) {
            float av[4] = { ra[i].x, ra[i].y, ra[i].z, ra[i].w };
            float bv[4] = { rb[i].x, rb[i].y, rb[i].z, rb[i].w };
#pragma unroll
            for (int e = 0; e < 4; e++) {
                As[lrow[i] * SS + e * 8 + lq[i]] = to_tf32(av[e]);
                Bs[lrow[i] * SS + e * 8 + lq[i]] = to_tf32(bv[e]);
            }
        }
        __syncthreads();

        if (k0 + BK < K) {
#pragma unroll
            for (int i = 0; i < 4; i++) {
                ra[i] = *(const float4*)(Ap + (size_t)lrow[i] * K + k0 + BK + lq[i] * 4);
                rb[i] = *(const float4*)(Wp + (size_t)lrow[i] * K + k0 + BK + lq[i] * 4);
            }
        }

#pragma unroll
        for (int s = 0; s < BK / 8; s++) {
            uint32_t af[4][4];
#pragma unroll
            for (int mi = 0; mi < 4; mi++) {
                int row = wm * 64 + mi * 16 + g;
                float2 lo0 = *(const float2*)&As[row * SS + tig * 8 + 2 * s];
                float2 lo1 = *(const float2*)&As[(row + 8) * SS + tig * 8 + 2 * s];
                af[mi][0] = __float_as_uint(lo0.x);
                af[mi][1] = __float_as_uint(lo1.x);
                af[mi][2] = __float_as_uint(lo0.y);
                af[mi][3] = __float_as_uint(lo1.y);
            }
            uint32_t bf[4][2];
#pragma unroll
            for (int ni = 0; ni < 4; ni++) {
                int row = wn * 32 + ni * 8 + g;
                float2 b = *(const float2*)&Bs[row * SS + tig * 8 + 2 * s];
                bf[ni][0] = __float_as_uint(b.x);
                bf[ni][1] = __float_as_uint(b.y);
            }
#pragma unroll
            for (int mi = 0; mi < 4; mi++)
#pragma unroll
                for (int ni = 0; ni < 4; ni++)
                    mma_tf32(acc[mi][ni], af[mi], bf[ni]);
        }
        __syncthreads();
    }

#pragma unroll
    for (int mi = 0; mi < 4; mi++) {
#pragma unroll
        for (int ni = 0; ni < 4; ni++) {
#pragma unroll
            for (int c = 0; c < 4; c++) {
                int m = m0 + wm * 64 + mi * 16 + g + (c >> 1) * 8;
                int n = n0 + wn * 32 + ni * 8 + tig * 2 + (c & 1);
                float v = acc[mi][ni][c] + bias[n];
                if (cmode == 0) {
                    Cout[(size_t)m * N + n] = v;
                } else {
                    int bb = m >> 11, ss = m & 2047;
                    int h = n >> 6, hd = n & 63;
                    if (cmode == 1) {
                        g_Q[(((size_t)(bb * NH + h)) * NS + ss) * HDIM + hd] = v;
                    } else if (cmode == 2) {
                        size_t off = (((size_t)(bb * NH + h)) * HDIM + hd) * NS
                                   + (ss & ~63) + ((ss & 7) * 8 + ((ss >> 3) & 7));
                        g_K[off] = to_tf32(v);
                    } else {
                        size_t off = (((size_t)(bb * NH + h)) * NS + ss) * HDIM
                                   + ((hd & 7) * 8 + (hd >> 3));
                        g_V[off] = to_tf32(v);
                    }
                }
            }
        }
    }
}

// ---------------------------------------------------------------------------
// Tensor-core flash attention, tf32 mma, causal.
// CTA: 256 q-rows of one (b,h); 8 warps x 32 rows (2 m16 tiles each).
// K-tiles of 64, double-buffered cp.async.  grid = (8, 64).
// ---------------------------------------------------------------------------
#define KSS 68
#define QROWS 256
#define FLASH_SMEM ((4*64*KSS + QROWS*KSS) * 4)   // 139264 B

__global__ __launch_bounds__(256, 1) void flash_attn_mma()
{
    extern __shared__ float sm[];
    float* KsA[2] = { sm,            sm + 64*KSS };
    float* VsA[2] = { sm + 2*64*KSS, sm + 3*64*KSS };
    float* Ps     = sm + 4*64*KSS;   // [QROWS][KSS]; doubles as Q staging

    const int tid  = threadIdx.x;
    const int lane = tid & 31;
    const int wq   = tid >> 5;            // 0..7
    const int g    = lane >> 2;           // 0..7
    const int tig  = lane & 3;            // 0..3
    const int bh   = blockIdx.y;
    const int qt   = (int)gridDim.x - 1 - (int)blockIdx.x;  // heavy first
    const int q0   = qt * QROWS;

    const float* Qb = g_Q + (size_t)bh * NS * HDIM;
    const float* Kb = g_K + (size_t)bh * HDIM * NS;   // [d][key(perm)]
    const float* Vb = g_V + (size_t)bh * NS * HDIM;   // [key][d(perm)]

    // ---- stage Q tile (256x64) into Ps, build Q frags ----
#pragma unroll
    for (int i = 0; i < 16; i++) {
        int f4 = tid + i * 256;           // 0..4095
        int row = f4 >> 4, c = (f4 & 15) * 4;
        *(float4*)&Ps[row * KSS + c] =
            *(const float4*)(Qb + (size_t)(q0 + row) * HDIM + c);
    }
    __syncthreads();

    float qf[2][8][4];
#pragma unroll
    for (int mi = 0; mi < 2; mi++) {
        const float* Q0 = &Ps[(wq * 32 + mi * 16 + g) * KSS];
        const float* Q1 = &Ps[(wq * 32 + mi * 16 + g + 8) * KSS];
#pragma unroll
        for (int s = 0; s < 8; s++) {
            qf[mi][s][0] = to_tf32(Q0[8 * s + tig] * 0.125f);
            qf[mi][s][1] = to_tf32(Q1[8 * s + tig] * 0.125f);
            qf[mi][s][2] = to_tf32(Q0[8 * s + tig + 4] * 0.125f);
            qf[mi][s][3] = to_tf32(Q1[8 * s + tig + 4] * 0.125f);
        }
    }
    __syncthreads();

    const int ktmax    = 4 * qt + 3;
    const int wrow_min = q0 + wq * 32;
    const int wrow_max = wrow_min + 31;

    auto prefetch = [&](int t) {
        int buf = t & 1;
        float* kd = KsA[buf];
        float* vd = VsA[buf];
        int kk0 = t * 64;
#pragma unroll
        for (int i = 0; i < 4; i++) {
            int f4 = tid + i * 256;       // 0..1023
            int row = f4 >> 4, c = (f4 & 15) * 4;
            cp16(&kd[row * KSS + c], Kb + (size_t)row * NS + kk0 + c);
            cp16(&vd[row * KSS + c], Vb + (size_t)(kk0 + row) * HDIM + c);
        }
    };

    prefetch(0);
    cp_commit();

    float oacc[2][8][4];
#pragma unroll
    for (int mi = 0; mi < 2; mi++)
#pragma unroll
        for (int i = 0; i < 8; i++)
#pragma unroll
            for (int c = 0; c < 4; c++) oacc[mi][i][c] = 0.0f;
    float mx[2][2] = { {-INFINITY, -INFINITY}, {-INFINITY, -INFINITY} };
    float ls[2][2] = { {0.0f, 0.0f}, {0.0f, 0.0f} };
    float* Pw = Ps + (wq * 32) * KSS;

    for (int kt = 0; kt <= ktmax; kt++) {
        cp_wait0();
        __syncthreads();
        if (kt < ktmax) { prefetch(kt + 1); cp_commit(); }

        const int k0 = kt * 64;
        if (k0 <= wrow_max) {
            const float* K = KsA[kt & 1];
            const float* V = VsA[kt & 1];

            // ---- S = Q K^T ----
            float sacc[2][8][4];
#pragma unroll
            for (int mi = 0; mi < 2; mi++)
#pragma unroll
                for (int i = 0; i < 8; i++)
#pragma unroll
                    for (int c = 0; c < 4; c++) sacc[mi][i][c] = 0.0f;

#pragma unroll
            for (int s = 0; s < 8; s++) {
                float k0a[8], k1a[8];
                const float* kr0 = &K[(8 * s + tig) * KSS + 8 * g];
                const float* kr1 = &K[(8 * s + tig + 4) * KSS + 8 * g];
                *(float4*)&k0a[0] = *(const float4*)&kr0[0];
                *(float4*)&k0a[4] = *(const float4*)&kr0[4];
                *(float4*)&k1a[0] = *(const float4*)&kr1[0];
                *(float4*)&k1a[4] = *(const float4*)&kr1[4];
#pragma unroll
                for (int mi = 0; mi < 2; mi++) {
                    uint32_t a[4] = { __float_as_uint(qf[mi][s][0]),
                                      __float_as_uint(qf[mi][s][1]),
                                      __float_as_uint(qf[mi][s][2]),
                                      __float_as_uint(qf[mi][s][3]) };
#pragma unroll
                    for (int nt = 0; nt < 8; nt++) {
                        uint32_t b[2] = { __float_as_uint(k0a[nt]),
                                          __float_as_uint(k1a[nt]) };
                        mma_tf32(sacc[mi][nt], a, b);
                    }
                }
            }

            // ---- causal mask ----
            if (k0 + 63 > wrow_min) {
#pragma unroll
                for (int mi = 0; mi < 2; mi++) {
                    int r0 = wrow_min + mi * 16 + g, r1 = r0 + 8;
#pragma unroll
                    for (int nt = 0; nt < 8; nt++) {
                        int c0 = k0 + 8 * nt + 2 * tig;
                        if (c0     > r0) sacc[mi][nt][0] = -INFINITY;
                        if (c0 + 1 > r0) sacc[mi][nt][1] = -INFINITY;
                        if (c0     > r1) sacc[mi][nt][2] = -INFINITY;
                        if (c0 + 1 > r1) sacc[mi][nt][3] = -INFINITY;
                    }
                }
            }

            // ---- online softmax + P write ----
#pragma unroll
            for (int mi = 0; mi < 2; mi++) {
                float t0 = -INFINITY, t1 = -INFINITY;
#pragma unroll
                for (int nt = 0; nt < 8; nt++) {
                    t0 = fmaxf(t0, fmaxf(sacc[mi][nt][0], sacc[mi][nt][1]));
                    t1 = fmaxf(t1, fmaxf(sacc[mi][nt][2], sacc[mi][nt][3]));
                }
                t0 = fmaxf(t0, __shfl_xor_sync(0xffffffffu, t0, 1));
                t0 = fmaxf(t0, __shfl_xor_sync(0xffffffffu, t0, 2));
                t1 = fmaxf(t1, __shfl_xor_sync(0xffffffffu, t1, 1));
                t1 = fmaxf(t1, __shfl_xor_sync(0xffffffffu, t1, 2));
                float nm0 = fmaxf(mx[mi][0], t0), nm1 = fmaxf(mx[mi][1], t1);
                float corr0 = __expf(mx[mi][0] - nm0);
                float corr1 = __expf(mx[mi][1] - nm1);

                float* P0 = &Pw[(mi * 16 + g) * KSS];
                float* P1 = &Pw[(mi * 16 + g + 8) * KSS];
                float ps0 = 0.0f, ps1 = 0.0f;
#pragma unroll
                for (int nt = 0; nt < 8; nt++) {
                    float p0 = __expf(sacc[mi][nt][0] - nm0);
                    float p1 = __expf(sacc[mi][nt][1] - nm0);
                    float p2 = __expf(sacc[mi][nt][2] - nm1);
                    float p3 = __expf(sacc[mi][nt][3] - nm1);
                    ps0 += p0 + p1; ps1 += p2 + p3;
                    float2 lo = { to_tf32(p0), to_tf32(p1) };
                    float2 hi = { to_tf32(p2), to_tf32(p3) };
                    *(float2*)&P0[8 * nt + 2 * tig] = lo;
                    *(float2*)&P1[8 * nt + 2 * tig] = hi;
                }
                ps0 += __shfl_xor_sync(0xffffffffu, ps0, 1);
                ps0 += __shfl_xor_sync(0xffffffffu, ps0, 2);
                ps1 += __shfl_xor_sync(0xffffffffu, ps1, 1);
                ps1 += __shfl_xor_sync(0xffffffffu, ps1, 2);
                ls[mi][0] = ls[mi][0] * corr0 + ps0;
                ls[mi][1] = ls[mi][1] * corr1 + ps1;
                mx[mi][0] = nm0; mx[mi][1] = nm1;
#pragma unroll
                for (int nt = 0; nt < 8; nt++) {
                    oacc[mi][nt][0] *= corr0; oacc[mi][nt][1] *= corr0;
                    oacc[mi][nt][2] *= corr1; oacc[mi][nt][3] *= corr1;
                }
            }
            __syncwarp();

            // ---- O += P V ----
#pragma unroll
            for (int s = 0; s < 8; s++) {
                float v0a[8], v1a[8];
                const float* vr0 = &V[(8 * s + tig) * KSS + 8 * g];
                const float* vr1 = &V[(8 * s + tig + 4) * KSS + 8 * g];
                *(float4*)&v0a[0] = *(const float4*)&vr0[0];
                *(float4*)&v0a[4] = *(const float4*)&vr0[4];
                *(float4*)&v1a[0] = *(const float4*)&vr1[0];
                *(float4*)&v1a[4] = *(const float4*)&vr1[4];
#pragma unroll
                for (int mi = 0; mi < 2; mi++) {
                    const float* P0 = &Pw[(mi * 16 + g) * KSS + 8 * s];
                    const float* P1 = &Pw[(mi * 16 + g + 8) * KSS + 8 * s];
                    uint32_t a[4] = { __float_as_uint(P0[tig]),
                                      __float_as_uint(P1[tig]),
                                      __float_as_uint(P0[tig + 4]),
                                      __float_as_uint(P1[tig + 4]) };
#pragma unroll
                    for (int nt = 0; nt < 8; nt++) {
                        uint32_t b[2] = { __float_as_uint(v0a[nt]),
                                          __float_as_uint(v1a[nt]) };
                        mma_tf32(oacc[mi][nt], a, b);
                    }
                }
            }
            __syncwarp();
        }
    }

    // ---- epilogue ----
    int b = bh >> 4, h = bh & 15;
#pragma unroll
    for (int mi = 0; mi < 2; mi++) {
        float inv0 = 1.0f / ls[mi][0], inv1 = 1.0f / ls[mi][1];
        int row0 = q0 + wq * 32 + mi * 16 + g;
        float* O0 = g_AO + ((size_t)(b * NS + row0)) * ND + h * HDIM;
        float* O1 = g_AO + ((size_t)(b * NS + row0 + 8)) * ND + h * HDIM;
#pragma unroll
        for (int nt = 0; nt < 8; nt++) {
            float2 lo = { oacc[mi][nt][0] * inv0, oacc[mi][nt][1] * inv0 };
            float2 hi = { oacc[mi][nt][2] * inv1, oacc[mi][nt][3] * inv1 };
            *(float2*)&O0[8 * nt + 2 * tig] = lo;
            *(float2*)&O1[8 * nt + 2 * tig] = hi;
        }
    }
}

// ---------------------------------------------------------------------------
extern "C" void kernel_launch(void* const* d_in, const int* in_sizes, int n_in,
                              void* d_out, int out_size)
{
    const float* x    = (const float*)d_in[0];
    const float* wq_w = (const float*)d_in[1];
    const float* wq_b = (const float*)d_in[2];
    const float* wk_w = (const float*)d_in[3];
    const float* wk_b = (const float*)d_in[4];
    const float* wv_w = (const float*)d_in[5];
    const float* wv_b = (const float*)d_in[6];
    const float* wo_w = (const float*)d_in[7];
    const float* wo_b = (const float*)d_in[8];
    float* out = (float*)d_out;

    // Fused QKV projections (one launch, A tile read once)
    gemm_tf32<<<dim3(24, NM / 128), 256>>>(
        x, wq_w, wq_b, wk_w, wk_b, wv_w, wv_b, nullptr, 0, 1, 0);

    cudaFuncSetAttribute(flash_attn_mma,
                         cudaFuncAttributeMaxDynamicSharedMemorySize, FLASH_SMEM);
    flash_attn_mma<<<dim3(NS / QROWS, NB * NH), 256, FLASH_SMEM>>>();

    // Output projection -> d_out
    gemm_tf32<<<dim3(8, NM / 128), 256>>>(
        nullptr, wo_w, wo_b, nullptr, nullptr, nullptr, nullptr, out, 1, 0, 0);
}

// round 6
// speedup vs baseline: 7.2315x; 1.2175x over previous
#include <cuda_runtime.h>
#include <math.h>
#include <stdint.h>

#define NB 4
#define NS 2048
#define ND 1024
#define NH 16
#define HDIM 64
#define NM (NB*NS)   // 8192 rows
#define MM (ND*ND)

// Scratch (allocation-free rule: __device__ globals). ~182 MB total.
// g_Q: [bh][s][d]            (natural fp32)
// g_K: [bh][d][key]          key permuted per 64-block: pos=(k&7)*8+((k>>3)&7); tf32
// g_V: [bh][key][d']         d' = (d&7)*8 + (d>>3); tf32
// g_AO: attention out [B,S,D], tf32-rounded
// g_XP: tf32-rounded copy of x;  g_WP: tf32-rounded copies of Wq,Wk,Wv,Wo
__device__ __align__(256) float g_Q[(size_t)NB*NH*NS*HDIM];
__device__ __align__(256) float g_K[(size_t)NB*NH*NS*HDIM];
__device__ __align__(256) float g_V[(size_t)NB*NH*NS*HDIM];
__device__ __align__(256) float g_AO[(size_t)NB*NS*ND];
__device__ __align__(256) float g_XP[(size_t)NM*ND];
__device__ __align__(256) float g_WP[(size_t)4*MM];

__device__ __forceinline__ float to_tf32(float x) {
    float r;
    asm("cvt.rna.tf32.f32 %0, %1;" : "=f"(r) : "f"(x));
    return r;
}

__device__ __forceinline__ void mma_tf32(float d[4], const uint32_t a[4],
                                         const uint32_t b[2]) {
    asm volatile(
        "mma.sync.aligned.m16n8k8.row.col.f32.tf32.tf32.f32 "
        "{%0,%1,%2,%3},{%4,%5,%6,%7},{%8,%9},{%0,%1,%2,%3};"
        : "+f"(d[0]), "+f"(d[1]), "+f"(d[2]), "+f"(d[3])
        : "r"(a[0]), "r"(a[1]), "r"(a[2]), "r"(a[3]),
          "r"(b[0]), "r"(b[1]));
}

__device__ __forceinline__ void cp16(void* dst, const void* src) {
    uint32_t d = (uint32_t)__cvta_generic_to_shared(dst);
    asm volatile("cp.async.cg.shared.global [%0], [%1], 16;" :: "r"(d), "l"(src));
}
__device__ __forceinline__ void cp_commit() {
    asm volatile("cp.async.commit_group;" ::: "memory");
}
__device__ __forceinline__ void cp_wait0() {
    asm volatile("cp.async.wait_group 0;" ::: "memory");
}
__device__ __forceinline__ void cp_wait1() {
    asm volatile("cp.async.wait_group 1;" ::: "memory");
}

// ---------------------------------------------------------------------------
// Prep: round x and the 4 weight matrices to tf32 (RNA) into scratch.
// Avoids the systematic ~2^-10 truncation bias of feeding raw fp32 to HMMA.
// ---------------------------------------------------------------------------
__global__ __launch_bounds__(256) void prep_round(
    const float* __restrict__ x,
    const float* __restrict__ wq, const float* __restrict__ wk,
    const float* __restrict__ wv, const float* __restrict__ wo)
{
    const size_t XQ = (size_t)NM * ND / 4;   // 2M float4
    const size_t WQ = (size_t)MM / 4;        // 256K float4 per W
    size_t i = (size_t)blockIdx.x * 256 + threadIdx.x;
    if (i < XQ) {
        float4 v = ((const float4*)x)[i];
        v.x = to_tf32(v.x); v.y = to_tf32(v.y);
        v.z = to_tf32(v.z); v.w = to_tf32(v.w);
        ((float4*)g_XP)[i] = v;
    } else if (i < XQ + 4 * WQ) {
        size_t j = i - XQ;
        int w = (int)(j / WQ);
        size_t o = j - (size_t)w * WQ;
        const float* src = (w == 0) ? wq : (w == 1) ? wk : (w == 2) ? wv : wo;
        float4 v = ((const float4*)src)[o];
        v.x = to_tf32(v.x); v.y = to_tf32(v.y);
        v.z = to_tf32(v.z); v.w = to_tf32(v.w);
        ((float4*)g_WP)[j] = v;
    }
}

// ---------------------------------------------------------------------------
// C = A @ W^T + bias, TF32 mma.sync.  A:[M,K] rm (pre-rounded), W from g_WP.
// CTA 128x128x32, 4 warps (2m x 2n), warp tile 64x64, cp.async 2-stage.
// amode: 0 -> A = g_XP, 1 -> A = g_AO.
// fused=1: grid.x=24, sel=bx>>3 -> W_{q,k,v}, scatter cmode=sel+1.
// fused=0: W = g_WP[3] (Wo), cmode0.
// ---------------------------------------------------------------------------
#define SSg 36
#define GST (128*SSg)              // floats per A (or B) block
#define STAGE_F (2*GST)
#define GEMM_SMEM (2*STAGE_F*4)    // 73728 B

__global__ __launch_bounds__(128, 2) void gemm_tf32(
    const float* __restrict__ b0, const float* __restrict__ b1,
    const float* __restrict__ b2, float* __restrict__ Cout,
    int amode, int fused, int cmode0)
{
    extern __shared__ float smg[];

    const float* A = amode ? g_AO : g_XP;
    int sel, nblk, cmode;
    const float* bias;
    if (fused) {
        sel  = blockIdx.x >> 3;
        nblk = blockIdx.x & 7;
        bias = (sel == 0) ? b0 : (sel == 1) ? b1 : b2;
        cmode = sel + 1;
    } else {
        sel = 3; nblk = blockIdx.x;
        bias = b0; cmode = cmode0;
    }
    const float* W = g_WP + (size_t)sel * MM;

    const int tid  = threadIdx.x;
    const int lane = tid & 31;
    const int wid  = tid >> 5;       // 0..3
    const int wm   = wid & 1;
    const int wn   = wid >> 1;
    const int m0   = blockIdx.y * 128;
    const int n0   = nblk * 128;
    const int g    = lane >> 2;      // 0..7
    const int tig  = lane & 3;       // 0..3

    float acc[4][8][4];
#pragma unroll
    for (int i = 0; i < 4; i++)
#pragma unroll
        for (int j = 0; j < 8; j++)
#pragma unroll
            for (int c = 0; c < 4; c++) acc[i][j][c] = 0.0f;

    const float* Ap = A + (size_t)m0 * ND;
    const float* Wp = W + (size_t)n0 * ND;

    auto loadStage = [&](int c) {
        float* As = smg + (c & 1) * STAGE_F;
        float* Bs = As + GST;
#pragma unroll
        for (int i = 0; i < 8; i++) {
            int f = tid + i * 128;          // 0..1023
            int row = f >> 3, q = f & 7;
            cp16(&As[row * SSg + q * 4], Ap + (size_t)row * ND + c * 32 + q * 4);
            cp16(&Bs[row * SSg + q * 4], Wp + (size_t)row * ND + c * 32 + q * 4);
        }
    };

    loadStage(0);
    cp_commit();

    for (int c = 0; c < ND / 32; c++) {
        if (c + 1 < ND / 32) {
            loadStage(c + 1);
            cp_commit();
            cp_wait1();
        } else {
            cp_wait0();
        }
        __syncthreads();
        const float* As = smg + (c & 1) * STAGE_F;
        const float* Bs = As + GST;

#pragma unroll
        for (int s = 0; s < 4; s++) {
            uint32_t af[4][4];
#pragma unroll
            for (int mi = 0; mi < 4; mi++) {
                int r = wm * 64 + mi * 16 + g;
                const float* p0 = &As[r * SSg + 8 * s + tig];
                const float* p1 = &As[(r + 8) * SSg + 8 * s + tig];
                af[mi][0] = __float_as_uint(p0[0]);
                af[mi][1] = __float_as_uint(p1[0]);
                af[mi][2] = __float_as_uint(p0[4]);
                af[mi][3] = __float_as_uint(p1[4]);
            }
            uint32_t bf[8][2];
#pragma unroll
            for (int ni = 0; ni < 8; ni++) {
                const float* p = &Bs[(wn * 64 + ni * 8 + g) * SSg + 8 * s + tig];
                bf[ni][0] = __float_as_uint(p[0]);
                bf[ni][1] = __float_as_uint(p[4]);
            }
#pragma unroll
            for (int mi = 0; mi < 4; mi++)
#pragma unroll
                for (int ni = 0; ni < 8; ni++)
                    mma_tf32(acc[mi][ni], af[mi], bf[ni]);
        }
        __syncthreads();
    }

    // ---- epilogue ----
#pragma unroll
    for (int mi = 0; mi < 4; mi++) {
#pragma unroll
        for (int ni = 0; ni < 8; ni++) {
#pragma unroll
            for (int c = 0; c < 4; c++) {
                int m = m0 + wm * 64 + mi * 16 + g + (c >> 1) * 8;
                int n = n0 + wn * 64 + ni * 8 + tig * 2 + (c & 1);
                float v = acc[mi][ni][c] + bias[n];
                if (cmode == 0) {
                    Cout[(size_t)m * ND + n] = v;
                } else {
                    int bb = m >> 11, ss = m & 2047;
                    int h = n >> 6, hd = n & 63;
                    if (cmode == 1) {
                        g_Q[(((size_t)(bb * NH + h)) * NS + ss) * HDIM + hd] = v;
                    } else if (cmode == 2) {
                        size_t off = (((size_t)(bb * NH + h)) * HDIM + hd) * NS
                                   + (ss & ~63) + ((ss & 7) * 8 + ((ss >> 3) & 7));
                        g_K[off] = to_tf32(v);
                    } else {
                        size_t off = (((size_t)(bb * NH + h)) * NS + ss) * HDIM
                                   + ((hd & 7) * 8 + (hd >> 3));
                        g_V[off] = to_tf32(v);
                    }
                }
            }
        }
    }
}

// ---------------------------------------------------------------------------
// Tensor-core flash attention, tf32 mma, causal.
// CTA: 128 q-rows of one (b,h); 4 warps, each owns m16 tiles {wq, 7-wq}
// (balanced causal work).  K-tiles of 64, double-buffered cp.async.
// 2 CTAs/SM (smem 104448 x2).  grid = (16, 64).
// ---------------------------------------------------------------------------
#define KSS 68
#define QROWS 128
#define FLASH_SMEM ((4*64*KSS + QROWS*KSS) * 4)   // 104448 B

__global__ __launch_bounds__(128, 2) void flash_attn_mma()
{
    extern __shared__ float sm[];
    float* KsA[2] = { sm,            sm + 64*KSS };
    float* VsA[2] = { sm + 2*64*KSS, sm + 3*64*KSS };
    float* Ps     = sm + 4*64*KSS;   // [QROWS][KSS]; doubles as Q staging

    const int tid  = threadIdx.x;
    const int lane = tid & 31;
    const int wq   = tid >> 5;            // 0..3
    const int g    = lane >> 2;           // 0..7
    const int tig  = lane & 3;            // 0..3
    const int bh   = blockIdx.y;
    const int qt   = (int)gridDim.x - 1 - (int)blockIdx.x;  // heavy first
    const int q0   = qt * QROWS;

    const int tt[2]   = { wq, 7 - wq };                  // balanced m16 tiles
    const int trow[2] = { q0 + tt[0] * 16, q0 + tt[1] * 16 };

    const float* Qb = g_Q + (size_t)bh * NS * HDIM;
    const float* Kb = g_K + (size_t)bh * HDIM * NS;   // [d][key(perm)]
    const float* Vb = g_V + (size_t)bh * NS * HDIM;   // [key][d(perm)]

    // ---- stage Q tile (128x64) into Ps, build Q frags ----
#pragma unroll
    for (int i = 0; i < 16; i++) {
        int f4 = tid + i * 128;           // 0..2047
        int row = f4 >> 4, c = (f4 & 15) * 4;
        *(float4*)&Ps[row * KSS + c] =
            *(const float4*)(Qb + (size_t)(q0 + row) * HDIM + c);
    }
    __syncthreads();

    float qf[2][8][4];
#pragma unroll
    for (int mi = 0; mi < 2; mi++) {
        const float* Q0 = &Ps[(tt[mi] * 16 + g) * KSS];
        const float* Q1 = &Ps[(tt[mi] * 16 + g + 8) * KSS];
#pragma unroll
        for (int s = 0; s < 8; s++) {
            qf[mi][s][0] = to_tf32(Q0[8 * s + tig] * 0.125f);
            qf[mi][s][1] = to_tf32(Q1[8 * s + tig] * 0.125f);
            qf[mi][s][2] = to_tf32(Q0[8 * s + tig + 4] * 0.125f);
            qf[mi][s][3] = to_tf32(Q1[8 * s + tig + 4] * 0.125f);
        }
    }
    __syncthreads();

    const int ktmax = 2 * qt + 1;

    auto prefetch = [&](int t) {
        float* kd = KsA[t & 1];
        float* vd = VsA[t & 1];
        int kk0 = t * 64;
#pragma unroll
        for (int i = 0; i < 8; i++) {
            int f4 = tid + i * 128;       // 0..1023
            int row = f4 >> 4, c = (f4 & 15) * 4;
            cp16(&kd[row * KSS + c], Kb + (size_t)row * NS + kk0 + c);
            cp16(&vd[row * KSS + c], Vb + (size_t)(kk0 + row) * HDIM + c);
        }
    };

    prefetch(0);
    cp_commit();

    float oacc[2][8][4];
#pragma unroll
    for (int mi = 0; mi < 2; mi++)
#pragma unroll
        for (int i = 0; i < 8; i++)
#pragma unroll
            for (int c = 0; c < 4; c++) oacc[mi][i][c] = 0.0f;
    float mx[2][2] = { {-INFINITY, -INFINITY}, {-INFINITY, -INFINITY} };
    float ls[2][2] = { {0.0f, 0.0f}, {0.0f, 0.0f} };
    float* Pw = Ps + (wq * 32) * KSS;     // scratch rows for this warp

    for (int kt = 0; kt <= ktmax; kt++) {
        cp_wait0();
        __syncthreads();
        if (kt < ktmax) { prefetch(kt + 1); cp_commit(); }

        const int k0 = kt * 64;
        const bool act0 = (k0 <= trow[0] + 15);
        const bool act1 = (k0 <= trow[1] + 15);   // act0 implies act1
        if (act1) {
            const float* K = KsA[kt & 1];
            const float* V = VsA[kt & 1];

            // ---- S = Q K^T ----
            float sacc[2][8][4];
#pragma unroll
            for (int mi = 0; mi < 2; mi++)
#pragma unroll
                for (int i = 0; i < 8; i++)
#pragma unroll
                    for (int c = 0; c < 4; c++) sacc[mi][i][c] = 0.0f;

#pragma unroll
            for (int s = 0; s < 8; s++) {
                float k0a[8], k1a[8];
                const float* kr0 = &K[(8 * s + tig) * KSS + 8 * g];
                const float* kr1 = &K[(8 * s + tig + 4) * KSS + 8 * g];
                *(float4*)&k0a[0] = *(const float4*)&kr0[0];
                *(float4*)&k0a[4] = *(const float4*)&kr0[4];
                *(float4*)&k1a[0] = *(const float4*)&kr1[0];
                *(float4*)&k1a[4] = *(const float4*)&kr1[4];
#pragma unroll
                for (int mi = 0; mi < 2; mi++) {
                    if (mi == 0 && !act0) continue;
                    uint32_t a[4] = { __float_as_uint(qf[mi][s][0]),
                                      __float_as_uint(qf[mi][s][1]),
                                      __float_as_uint(qf[mi][s][2]),
                                      __float_as_uint(qf[mi][s][3]) };
#pragma unroll
                    for (int nt = 0; nt < 8; nt++) {
                        uint32_t b[2] = { __float_as_uint(k0a[nt]),
                                          __float_as_uint(k1a[nt]) };
                        mma_tf32(sacc[mi][nt], a, b);
                    }
                }
            }

            // ---- causal mask (per mi) ----
#pragma unroll
            for (int mi = 0; mi < 2; mi++) {
                if (mi == 0 && !act0) continue;
                if (k0 + 63 > trow[mi]) {
                    int r0 = trow[mi] + g, r1 = r0 + 8;
#pragma unroll
                    for (int nt = 0; nt < 8; nt++) {
                        int c0 = k0 + 8 * nt + 2 * tig;
                        if (c0     > r0) sacc[mi][nt][0] = -INFINITY;
                        if (c0 + 1 > r0) sacc[mi][nt][1] = -INFINITY;
                        if (c0     > r1) sacc[mi][nt][2] = -INFINITY;
                        if (c0 + 1 > r1) sacc[mi][nt][3] = -INFINITY;
                    }
                }
            }

            // ---- online softmax + P write ----
#pragma unroll
            for (int mi = 0; mi < 2; mi++) {
                if (mi == 0 && !act0) continue;
                float t0 = -INFINITY, t1 = -INFINITY;
#pragma unroll
                for (int nt = 0; nt < 8; nt++) {
                    t0 = fmaxf(t0, fmaxf(sacc[mi][nt][0], sacc[mi][nt][1]));
                    t1 = fmaxf(t1, fmaxf(sacc[mi][nt][2], sacc[mi][nt][3]));
                }
                t0 = fmaxf(t0, __shfl_xor_sync(0xffffffffu, t0, 1));
                t0 = fmaxf(t0, __shfl_xor_sync(0xffffffffu, t0, 2));
                t1 = fmaxf(t1, __shfl_xor_sync(0xffffffffu, t1, 1));
                t1 = fmaxf(t1, __shfl_xor_sync(0xffffffffu, t1, 2));
                float nm0 = fmaxf(mx[mi][0], t0), nm1 = fmaxf(mx[mi][1], t1);
                float corr0 = __expf(mx[mi][0] - nm0);
                float corr1 = __expf(mx[mi][1] - nm1);

                float* P0 = &Pw[(mi * 16 + g) * KSS];
                float* P1 = &Pw[(mi * 16 + g + 8) * KSS];
                float ps0 = 0.0f, ps1 = 0.0f;
#pragma unroll
                for (int nt = 0; nt < 8; nt++) {
                    float p0 = __expf(sacc[mi][nt][0] - nm0);
                    float p1 = __expf(sacc[mi][nt][1] - nm0);
                    float p2 = __expf(sacc[mi][nt][2] - nm1);
                    float p3 = __expf(sacc[mi][nt][3] - nm1);
                    ps0 += p0 + p1; ps1 += p2 + p3;
                    float2 lo = { to_tf32(p0), to_tf32(p1) };
                    float2 hi = { to_tf32(p2), to_tf32(p3) };
                    *(float2*)&P0[8 * nt + 2 * tig] = lo;
                    *(float2*)&P1[8 * nt + 2 * tig] = hi;
                }
                ps0 += __shfl_xor_sync(0xffffffffu, ps0, 1);
                ps0 += __shfl_xor_sync(0xffffffffu, ps0, 2);
                ps1 += __shfl_xor_sync(0xffffffffu, ps1, 1);
                ps1 += __shfl_xor_sync(0xffffffffu, ps1, 2);
                ls[mi][0] = ls[mi][0] * corr0 + ps0;
                ls[mi][1] = ls[mi][1] * corr1 + ps1;
                mx[mi][0] = nm0; mx[mi][1] = nm1;
#pragma unroll
                for (int nt = 0; nt < 8; nt++) {
                    oacc[mi][nt][0] *= corr0; oacc[mi][nt][1] *= corr0;
                    oacc[mi][nt][2] *= corr1; oacc[mi][nt][3] *= corr1;
                }
            }
            __syncwarp();

            // ---- O += P V ----
#pragma unroll
            for (int s = 0; s < 8; s++) {
                float v0a[8], v1a[8];
                const float* vr0 = &V[(8 * s + tig) * KSS + 8 * g];
                const float* vr1 = &V[(8 * s + tig + 4) * KSS + 8 * g];
                *(float4*)&v0a[0] = *(const float4*)&vr0[0];
                *(float4*)&v0a[4] = *(const float4*)&vr0[4];
                *(float4*)&v1a[0] = *(const float4*)&vr1[0];
                *(float4*)&v1a[4] = *(const float4*)&vr1[4];
#pragma unroll
                for (int mi = 0; mi < 2; mi++) {
                    if (mi == 0 && !act0) continue;
                    const float* P0 = &Pw[(mi * 16 + g) * KSS + 8 * s];
                    const float* P1 = &Pw[(mi * 16 + g + 8) * KSS + 8 * s];
                    uint32_t a[4] = { __float_as_uint(P0[tig]),
                                      __float_as_uint(P1[tig]),
                                      __float_as_uint(P0[tig + 4]),
                                      __float_as_uint(P1[tig + 4]) };
#pragma unroll
                    for (int nt = 0; nt < 8; nt++) {
                        uint32_t b[2] = { __float_as_uint(v0a[nt]),
                                          __float_as_uint(v1a[nt]) };
                        mma_tf32(oacc[mi][nt], a, b);
                    }
                }
            }
            __syncwarp();
        }
    }

    // ---- epilogue (tf32-rounded: g_AO feeds the out-GEMM tensor cores) ----
    int b = bh >> 4, h = bh & 15;
#pragma unroll
    for (int mi = 0; mi < 2; mi++) {
        float inv0 = 1.0f / ls[mi][0], inv1 = 1.0f / ls[mi][1];
        int row0 = trow[mi] + g;
        float* O0 = g_AO + ((size_t)(b * NS + row0)) * ND + h * HDIM;
        float* O1 = g_AO + ((size_t)(b * NS + row0 + 8)) * ND + h * HDIM;
#pragma unroll
        for (int nt = 0; nt < 8; nt++) {
            float2 lo = { to_tf32(oacc[mi][nt][0] * inv0),
                          to_tf32(oacc[mi][nt][1] * inv0) };
            float2 hi = { to_tf32(oacc[mi][nt][2] * inv1),
                          to_tf32(oacc[mi][nt][3] * inv1) };
            *(float2*)&O0[8 * nt + 2 * tig] = lo;
            *(float2*)&O1[8 * nt + 2 * tig] = hi;
        }
    }
}

// ---------------------------------------------------------------------------
extern "C" void kernel_launch(void* const* d_in, const int* in_sizes, int n_in,
                              void* d_out, int out_size)
{
    const float* x    = (const float*)d_in[0];
    const float* wq_w = (const float*)d_in[1];
    const float* wq_b = (const float*)d_in[2];
    const float* wk_w = (const float*)d_in[3];
    const float* wk_b = (const float*)d_in[4];
    const float* wv_w = (const float*)d_in[5];
    const float* wv_b = (const float*)d_in[6];
    const float* wo_w = (const float*)d_in[7];
    const float* wo_b = (const float*)d_in[8];
    float* out = (float*)d_out;

    cudaFuncSetAttribute(gemm_tf32, cudaFuncAttributeMaxDynamicSharedMemorySize,
                         GEMM_SMEM);
    cudaFuncSetAttribute(flash_attn_mma,
                         cudaFuncAttributeMaxDynamicSharedMemorySize, FLASH_SMEM);

    // Round x and weights to tf32 (RNA) once.
    int prep_blocks = (int)(((size_t)NM * ND / 4 + (size_t)MM) / 256);
    prep_round<<<prep_blocks, 256>>>(x, wq_w, wk_w, wv_w, wo_w);

    // Fused QKV projections
    gemm_tf32<<<dim3(24, NM / 128), 128, GEMM_SMEM>>>(
        wq_b, wk_b, wv_b, nullptr, 0, 1, 0);

    flash_attn_mma<<<dim3(NS / QROWS, NB * NH), 128, FLASH_SMEM>>>();

    // Output projection -> d_out
    gemm_tf32<<<dim3(8, NM / 128), 128, GEMM_SMEM>>>(
        wo_b, nullptr, nullptr, out, 1, 0, 0);
}